// round 7
// baseline (speedup 1.0000x reference)
#include <cuda_runtime.h>
#include <cuda_fp16.h>

// Problem constants (fixed-shape problem)
#define NN 100000
#define DD 64
#define D2 32              // half2 elements per row
#define EE 1600000
#define DTC 0.2f

// ---------------- scratch (device globals: no runtime allocation) ------------
__device__ int      g_deg_r[NN];
__device__ int      g_deg_c[NN];
__device__ int      g_start[NN];
__device__ int      g_fill[NN];
__device__ float    g_dinv_r[NN];
__device__ float    g_dinv_c[NN];
__device__ float    g_maskf[NN];
__device__ int      g_cursor;
__device__ unsigned g_erec[EE];      // (col<<15) | (fp16 weight bits, sign=0)
__device__ uint4    g_yh[NN * 8];    // masked stage input, fp16 x8 per uint4
__device__ uint4    g_th[NN * 8];    // hop-1 output, fp16
__device__ float    g_accf[NN * DD]; // k1 + 2k2 + 2k3 (fp32)

// ---------------- helpers ----------------------------------------------------
__device__ __forceinline__ uint4 pack8h(const float* v) {
    union { __half2 h[4]; uint4 u; } p;
    p.h[0] = __floats2half2_rn(v[0], v[1]);
    p.h[1] = __floats2half2_rn(v[2], v[3]);
    p.h[2] = __floats2half2_rn(v[4], v[5]);
    p.h[3] = __floats2half2_rn(v[6], v[7]);
    return p.u;
}

// ---------------- CSR build --------------------------------------------------
__global__ void k_zero() {
    int i = blockIdx.x * blockDim.x + threadIdx.x;
    if (i < NN) { g_deg_r[i] = 0; g_deg_c[i] = 0; }
    if (i == 0) g_cursor = 0;
}

__global__ void k_count(const int* __restrict__ row, const int* __restrict__ col) {
    int e = blockIdx.x * blockDim.x + threadIdx.x;
    if (e < EE) {
        atomicAdd(&g_deg_r[row[e]], 1);
        atomicAdd(&g_deg_c[col[e]], 1);
    }
}

// Warp-aggregated segment assignment + per-node factors + mask image.
__global__ void k_start(const int* __restrict__ mask) {
    int i = blockIdx.x * blockDim.x + threadIdx.x;
    int lane = threadIdx.x & 31;
    int deg = (i < NN) ? g_deg_r[i] : 0;
    int s = deg;
    #pragma unroll
    for (int o = 1; o < 32; o <<= 1) {
        int t = __shfl_up_sync(0xFFFFFFFFu, s, o);
        if (lane >= o) s += t;
    }
    int total = __shfl_sync(0xFFFFFFFFu, s, 31);
    int base = 0;
    if (lane == 31) base = atomicAdd(&g_cursor, total);
    base = __shfl_sync(0xFFFFFFFFu, base, 31);
    int start = base + s - deg;
    if (i < NN) {
        g_start[i] = start;
        g_fill[i]  = start;
        g_dinv_r[i] = (deg > 0) ? rsqrtf((float)deg) : 0.f;
        int dc = g_deg_c[i];
        g_dinv_c[i] = (dc > 0) ? rsqrtf((float)dc) : 0.f;
        g_maskf[i] = (float)mask[i];
    }
}

// fp16 masked image of r0
__global__ void k_prep(const float2* __restrict__ r0) {
    int i = blockIdx.x * blockDim.x + threadIdx.x;  // over NN*D2 half2 slots
    if (i < NN * D2) {
        float mf = g_maskf[i >> 5];
        float2 v = r0[i];
        ((__half2*)g_yh)[i] = __float22half2_rn(make_float2(mf * v.x, mf * v.y));
    }
}

__global__ void k_fill(const int* __restrict__ row, const int* __restrict__ col) {
    int e = blockIdx.x * blockDim.x + threadIdx.x;
    if (e < EE) {
        int r = row[e], c = col[e];
        int p = atomicAdd(&g_fill[r], 1);
        float w = g_dinv_r[r] * g_dinv_c[c];
        unsigned hb = (unsigned)__half_as_ushort(__float2half_rn(w)); // sign=0
        g_erec[p] = ((unsigned)c << 15) | hb;   // 17b col | 15b weight
    }
}

// ---------------- SpMM -------------------------------------------------------
// Warp per row. Quarter-warp per edge: q = lane>>3 edge slot, fl = lane&7
// feature slot (8 fp16 = one float4). One LDG.128 per warp gathers 4 edges'
// row chunks. Packed edge records loaded 32-wide, broadcast via shfl.
// Inner loop is software-pipelined (depth 2): next group's shfl+gather is
// issued before the current group's FMAs, doubling per-warp gather MLP.
//
// MODE H1:    tmp = A * y_h                       (write g_th fp16)
// MODE INIT:  k = -A*tmp; acc = k;   y_h = fp16(mask*(r + c*k))
// MODE ACC:   k = -A*tmp; acc += 2k; y_h = fp16(mask*(r + c*k))
// MODE FINAL: k = -A*tmp; rn = r + DT/6*(acc+k); y_h = fp16(mask*rn)
#define M_H1    0
#define M_INIT  1
#define M_ACC   2
#define M_FINAL 3

template<int MODE>
__global__ void __launch_bounds__(256)
k_spmm(float4* __restrict__ outr, const float4* __restrict__ rr, float c) {
    int w = (blockIdx.x * blockDim.x + threadIdx.x) >> 5;
    if (w >= NN) return;
    int lane = threadIdx.x & 31;
    int q  = lane >> 3;
    int fl = lane & 7;

    const float4* x = (const float4*)((MODE == M_H1) ? g_yh : g_th);
    const int start = g_start[w];
    const int deg   = g_deg_r[w];
    const unsigned* ep = g_erec + start;

    float acc[8];
    #pragma unroll
    for (int t = 0; t < 8; t++) acc[t] = 0.f;

    for (int base = 0; base < deg; base += 32) {
        int rem = deg - base;
        int nE = rem < 32 ? rem : 32;
        // one record per lane; inactive lanes get rec=0 -> col 0, weight 0
        unsigned my = (lane < nE) ? __ldg(ep + base + lane) : 0u;

        // pipelined groups of 4 edges
        unsigned rec = __shfl_sync(0xFFFFFFFFu, my, q);
        float4 hv = __ldg(x + (rec >> 15) * 8 + fl);
        for (int j = 4; j < nE; j += 4) {
            unsigned rec_n = __shfl_sync(0xFFFFFFFFu, my, j + q);
            float4 hv_n = __ldg(x + (rec_n >> 15) * 8 + fl);
            float wgt = __half2float(__ushort_as_half((unsigned short)(rec & 0x7FFFu)));
            const __half2* hp = (const __half2*)&hv;
            #pragma unroll
            for (int t = 0; t < 4; t++) {
                float2 v = __half22float2(hp[t]);
                acc[2*t]   = fmaf(wgt, v.x, acc[2*t]);
                acc[2*t+1] = fmaf(wgt, v.y, acc[2*t+1]);
            }
            rec = rec_n; hv = hv_n;
        }
        // drain last pending group
        {
            float wgt = __half2float(__ushort_as_half((unsigned short)(rec & 0x7FFFu)));
            const __half2* hp = (const __half2*)&hv;
            #pragma unroll
            for (int t = 0; t < 4; t++) {
                float2 v = __half22float2(hp[t]);
                acc[2*t]   = fmaf(wgt, v.x, acc[2*t]);
                acc[2*t+1] = fmaf(wgt, v.y, acc[2*t+1]);
            }
        }
    }
    #pragma unroll
    for (int t = 0; t < 8; t++) {
        acc[t] += __shfl_xor_sync(0xFFFFFFFFu, acc[t], 8);
        acc[t] += __shfl_xor_sync(0xFFFFFFFFu, acc[t], 16);
    }
    if (q != 0) return;      // 8 lanes hold the full row

    int i8  = w * 8 + fl;        // uint4 index into fp16 images
    int i16 = w * 16 + fl * 2;   // float4 index into fp32 arrays

    if (MODE == M_H1) {
        g_th[i8] = pack8h(acc);
        return;
    }

    float kx[8];
    #pragma unroll
    for (int t = 0; t < 8; t++) kx[t] = -acc[t];   // fold -ETA
    float mf = g_maskf[w];
    float4 r1 = __ldg(rr + i16);
    float4 r2 = __ldg(rr + i16 + 1);
    float rr8[8] = { r1.x, r1.y, r1.z, r1.w, r2.x, r2.y, r2.z, r2.w };
    float4* accp = (float4*)g_accf;

    if (MODE == M_FINAL) {
        float4 a1 = accp[i16], a2 = accp[i16 + 1];
        float a8[8] = { a1.x, a1.y, a1.z, a1.w, a2.x, a2.y, a2.z, a2.w };
        const float f = DTC / 6.f;
        float n8[8], y8[8];
        #pragma unroll
        for (int t = 0; t < 8; t++) {
            n8[t] = rr8[t] + f * (a8[t] + kx[t]);
            y8[t] = mf * n8[t];
        }
        outr[i16]     = make_float4(n8[0], n8[1], n8[2], n8[3]);
        outr[i16 + 1] = make_float4(n8[4], n8[5], n8[6], n8[7]);
        g_yh[i8] = pack8h(y8);
    } else {
        float a8[8];
        if (MODE == M_INIT) {
            #pragma unroll
            for (int t = 0; t < 8; t++) a8[t] = kx[t];
        } else {
            float4 a1 = accp[i16], a2 = accp[i16 + 1];
            float ld[8] = { a1.x, a1.y, a1.z, a1.w, a2.x, a2.y, a2.z, a2.w };
            #pragma unroll
            for (int t = 0; t < 8; t++) a8[t] = fmaf(2.f, kx[t], ld[t]);
        }
        accp[i16]     = make_float4(a8[0], a8[1], a8[2], a8[3]);
        accp[i16 + 1] = make_float4(a8[4], a8[5], a8[6], a8[7]);
        float y8[8];
        #pragma unroll
        for (int t = 0; t < 8; t++) y8[t] = mf * fmaf(c, kx[t], rr8[t]);
        g_yh[i8] = pack8h(y8);
    }
}

// ---------------- launcher ---------------------------------------------------
extern "C" void kernel_launch(void* const* d_in, const int* in_sizes, int n_in,
                              void* d_out, int out_size) {
    const float* r0  = (const float*)d_in[0];
    const int*   ei  = (const int*)d_in[1];
    const int*   msk = (const int*)d_in[2];
    const int* row = ei;
    const int* col = ei + EE;
    float* out = (float*)d_out;
    const size_t nd = (size_t)NN * DD;

    cudaMemcpyAsync(out, r0, nd * sizeof(float), cudaMemcpyDeviceToDevice);

    k_zero <<<(NN + 255) / 256, 256>>>();
    k_count<<<(EE + 255) / 256, 256>>>(row, col);
    k_start<<<(NN + 255) / 256, 256>>>(msk);
    k_fill <<<(EE + 255) / 256, 256>>>(row, col);
    k_prep <<<(NN * D2 + 255) / 256, 256>>>((const float2*)r0);

    const int B = (NN + 7) / 8;     // 8 warps of 32 per 256-thread block

    for (int s = 0; s < 5; s++) {
        const float4* r  = (const float4*)(out + (size_t)s * nd);
        float4*       rn = (float4*)(out + (size_t)(s + 1) * nd);

        // stage 1
        k_spmm<M_H1>   <<<B, 256>>>(nullptr, nullptr, 0.f);
        k_spmm<M_INIT> <<<B, 256>>>(nullptr, r, 0.5f * DTC);
        // stage 2
        k_spmm<M_H1>   <<<B, 256>>>(nullptr, nullptr, 0.f);
        k_spmm<M_ACC>  <<<B, 256>>>(nullptr, r, 0.5f * DTC);
        // stage 3
        k_spmm<M_H1>   <<<B, 256>>>(nullptr, nullptr, 0.f);
        k_spmm<M_ACC>  <<<B, 256>>>(nullptr, r, DTC);
        // stage 4
        k_spmm<M_H1>   <<<B, 256>>>(nullptr, nullptr, 0.f);
        k_spmm<M_FINAL><<<B, 256>>>(rn, r, 0.f);
    }
}

// round 8
// speedup vs baseline: 1.0582x; 1.0582x over previous
#include <cuda_runtime.h>
#include <cuda_fp16.h>

// Problem constants (fixed-shape problem)
#define NN 100000
#define DD 64
#define D2 32              // half2 elements per row
#define EE 1600000
#define DTC 0.2f

// ---------------- scratch (device globals: no runtime allocation) ------------
__device__ int     g_deg_r[NN];
__device__ int     g_deg_c[NN];
__device__ int     g_start[NN];
__device__ int     g_fill[NN];
__device__ float   g_dinv_r[NN];
__device__ float   g_dinv_c[NN];
__device__ float   g_maskf[NN];
__device__ int     g_cursor;
__device__ int2    g_edge[EE];        // {col, fp32 w = dinv_r*dinv_c}
__device__ uint4   g_yh[NN * 8];      // masked stage input, fp16 x8 per uint4
__device__ uint4   g_th[NN * 8];      // hop-1 output, fp16
__device__ float   g_accf[NN * DD];   // k1 + 2k2 + 2k3 (fp32)

// ---------------- helpers ----------------------------------------------------
__device__ __forceinline__ uint4 pack8h(const float* v) {
    union { __half2 h[4]; uint4 u; } p;
    p.h[0] = __floats2half2_rn(v[0], v[1]);
    p.h[1] = __floats2half2_rn(v[2], v[3]);
    p.h[2] = __floats2half2_rn(v[4], v[5]);
    p.h[3] = __floats2half2_rn(v[6], v[7]);
    return p.u;
}

// ---------------- CSR build --------------------------------------------------
__global__ void k_zero() {
    int i = blockIdx.x * blockDim.x + threadIdx.x;
    if (i < NN) { g_deg_r[i] = 0; g_deg_c[i] = 0; }
    if (i == 0) g_cursor = 0;
}

__global__ void k_count(const int* __restrict__ row, const int* __restrict__ col) {
    int e = blockIdx.x * blockDim.x + threadIdx.x;
    if (e < EE) {
        atomicAdd(&g_deg_r[row[e]], 1);
        atomicAdd(&g_deg_c[col[e]], 1);
    }
}

// Warp-aggregated segment assignment + per-node factors + mask image.
__global__ void k_start(const int* __restrict__ mask) {
    int i = blockIdx.x * blockDim.x + threadIdx.x;
    int lane = threadIdx.x & 31;
    int deg = (i < NN) ? g_deg_r[i] : 0;
    int s = deg;
    #pragma unroll
    for (int o = 1; o < 32; o <<= 1) {
        int t = __shfl_up_sync(0xFFFFFFFFu, s, o);
        if (lane >= o) s += t;
    }
    int total = __shfl_sync(0xFFFFFFFFu, s, 31);
    int base = 0;
    if (lane == 31) base = atomicAdd(&g_cursor, total);
    base = __shfl_sync(0xFFFFFFFFu, base, 31);
    int start = base + s - deg;
    if (i < NN) {
        g_start[i] = start;
        g_fill[i]  = start;
        g_dinv_r[i] = (deg > 0) ? rsqrtf((float)deg) : 0.f;
        int dc = g_deg_c[i];
        g_dinv_c[i] = (dc > 0) ? rsqrtf((float)dc) : 0.f;
        g_maskf[i] = (float)mask[i];
    }
}

__global__ void k_fill(const int* __restrict__ row, const int* __restrict__ col) {
    int e = blockIdx.x * blockDim.x + threadIdx.x;
    if (e < EE) {
        int r = row[e], c = col[e];
        int p = atomicAdd(&g_fill[r], 1);
        float w = g_dinv_r[r] * g_dinv_c[c];
        g_edge[p] = make_int2(c, __float_as_int(w));
    }
}

// fp16 masked image of r0
__global__ void k_prep(const float2* __restrict__ r0) {
    int i = blockIdx.x * blockDim.x + threadIdx.x;
    if (i < NN * D2) {
        float mf = g_maskf[i >> 5];
        float2 v = r0[i];
        ((__half2*)g_yh)[i] = __float22half2_rn(make_float2(mf * v.x, mf * v.y));
    }
}

// ---------------- SpMM -------------------------------------------------------
// Warp per row. Quarter-warp per edge: q = lane>>3 edge slot, fl = lane&7
// feature slot (8 fp16 = one float4 of the row image).
// Inner loop: fixed batch of 8 groups (32 edges), records loaded DIRECTLY by
// each quarter (8 lanes, same address -> LSU broadcast), predicated off past
// deg. The 8 record->gather chains are independent, so the hardware holds ~8
// records + 8 gathers in flight instead of serializing shfl->LDG per group.
// Dummy groups gather row 0 with weight 0 (L1-resident after first touch).
//
// MODE H1:    tmp = A * y_h                       (write g_th fp16)
// MODE INIT:  k = -A*tmp; acc = k;   y_h = fp16(mask*(r + c*k))
// MODE ACC:   k = -A*tmp; acc += 2k; y_h = fp16(mask*(r + c*k))
// MODE FINAL: k = -A*tmp; rn = r + DT/6*(acc+k); y_h = fp16(mask*rn)
#define M_H1    0
#define M_INIT  1
#define M_ACC   2
#define M_FINAL 3

template<int MODE>
__global__ void __launch_bounds__(256)
k_spmm(float4* __restrict__ outr, const float4* __restrict__ rr, float c) {
    int w = (blockIdx.x * blockDim.x + threadIdx.x) >> 5;
    if (w >= NN) return;
    int lane = threadIdx.x & 31;
    int q  = lane >> 3;
    int fl = lane & 7;

    const float4* x = (const float4*)((MODE == M_H1) ? g_yh : g_th);
    const int start = g_start[w];
    const int deg   = g_deg_r[w];
    const int2* ep = g_edge + start;

    float acc[8];
    #pragma unroll
    for (int t = 0; t < 8; t++) acc[t] = 0.f;

    for (int base = 0; base < deg; base += 32) {
        int2 m[8];
        #pragma unroll
        for (int j = 0; j < 8; j++) {
            int e = base + j * 4 + q;
            m[j] = (e < deg) ? __ldg(ep + e) : make_int2(0, 0);
        }
        #pragma unroll
        for (int j = 0; j < 8; j++) {
            float4 hv = __ldg(x + m[j].x * 8 + fl);
            float wgt = __int_as_float(m[j].y);
            const __half2* hp = (const __half2*)&hv;
            #pragma unroll
            for (int t = 0; t < 4; t++) {
                float2 v = __half22float2(hp[t]);
                acc[2*t]   = fmaf(wgt, v.x, acc[2*t]);
                acc[2*t+1] = fmaf(wgt, v.y, acc[2*t+1]);
            }
        }
    }
    #pragma unroll
    for (int t = 0; t < 8; t++) {
        acc[t] += __shfl_xor_sync(0xFFFFFFFFu, acc[t], 8);
        acc[t] += __shfl_xor_sync(0xFFFFFFFFu, acc[t], 16);
    }
    if (q != 0) return;      // 8 lanes hold the full row

    int i8  = w * 8 + fl;        // uint4 index into fp16 images
    int i16 = w * 16 + fl * 2;   // float4 index into fp32 arrays

    if (MODE == M_H1) {
        g_th[i8] = pack8h(acc);
        return;
    }

    float kx[8];
    #pragma unroll
    for (int t = 0; t < 8; t++) kx[t] = -acc[t];   // fold -ETA
    float mf = g_maskf[w];
    float4 r1 = __ldg(rr + i16);
    float4 r2 = __ldg(rr + i16 + 1);
    float rr8[8] = { r1.x, r1.y, r1.z, r1.w, r2.x, r2.y, r2.z, r2.w };
    float4* accp = (float4*)g_accf;

    if (MODE == M_FINAL) {
        float4 a1 = accp[i16], a2 = accp[i16 + 1];
        float a8[8] = { a1.x, a1.y, a1.z, a1.w, a2.x, a2.y, a2.z, a2.w };
        const float f = DTC / 6.f;
        float n8[8], y8[8];
        #pragma unroll
        for (int t = 0; t < 8; t++) {
            n8[t] = rr8[t] + f * (a8[t] + kx[t]);
            y8[t] = mf * n8[t];
        }
        outr[i16]     = make_float4(n8[0], n8[1], n8[2], n8[3]);
        outr[i16 + 1] = make_float4(n8[4], n8[5], n8[6], n8[7]);
        g_yh[i8] = pack8h(y8);
    } else {
        float a8[8];
        if (MODE == M_INIT) {
            #pragma unroll
            for (int t = 0; t < 8; t++) a8[t] = kx[t];
        } else {
            float4 a1 = accp[i16], a2 = accp[i16 + 1];
            float ld[8] = { a1.x, a1.y, a1.z, a1.w, a2.x, a2.y, a2.z, a2.w };
            #pragma unroll
            for (int t = 0; t < 8; t++) a8[t] = fmaf(2.f, kx[t], ld[t]);
        }
        accp[i16]     = make_float4(a8[0], a8[1], a8[2], a8[3]);
        accp[i16 + 1] = make_float4(a8[4], a8[5], a8[6], a8[7]);
        float y8[8];
        #pragma unroll
        for (int t = 0; t < 8; t++) y8[t] = mf * fmaf(c, kx[t], rr8[t]);
        g_yh[i8] = pack8h(y8);
    }
}

// ---------------- launcher ---------------------------------------------------
extern "C" void kernel_launch(void* const* d_in, const int* in_sizes, int n_in,
                              void* d_out, int out_size) {
    const float* r0  = (const float*)d_in[0];
    const int*   ei  = (const int*)d_in[1];
    const int*   msk = (const int*)d_in[2];
    const int* row = ei;
    const int* col = ei + EE;
    float* out = (float*)d_out;
    const size_t nd = (size_t)NN * DD;

    cudaMemcpyAsync(out, r0, nd * sizeof(float), cudaMemcpyDeviceToDevice);

    k_zero <<<(NN + 255) / 256, 256>>>();
    k_count<<<(EE + 255) / 256, 256>>>(row, col);
    k_start<<<(NN + 255) / 256, 256>>>(msk);
    k_fill <<<(EE + 255) / 256, 256>>>(row, col);
    k_prep <<<(NN * D2 + 255) / 256, 256>>>((const float2*)r0);

    const int B = (NN + 7) / 8;     // 8 warps of 32 per 256-thread block

    for (int s = 0; s < 5; s++) {
        const float4* r  = (const float4*)(out + (size_t)s * nd);
        float4*       rn = (float4*)(out + (size_t)(s + 1) * nd);

        // stage 1
        k_spmm<M_H1>   <<<B, 256>>>(nullptr, nullptr, 0.f);
        k_spmm<M_INIT> <<<B, 256>>>(nullptr, r, 0.5f * DTC);
        // stage 2
        k_spmm<M_H1>   <<<B, 256>>>(nullptr, nullptr, 0.f);
        k_spmm<M_ACC>  <<<B, 256>>>(nullptr, r, 0.5f * DTC);
        // stage 3
        k_spmm<M_H1>   <<<B, 256>>>(nullptr, nullptr, 0.f);
        k_spmm<M_ACC>  <<<B, 256>>>(nullptr, r, DTC);
        // stage 4
        k_spmm<M_H1>   <<<B, 256>>>(nullptr, nullptr, 0.f);
        k_spmm<M_FINAL><<<B, 256>>>(rn, r, 0.f);
    }
}